// round 1
// baseline (speedup 1.0000x reference)
#include <cuda_runtime.h>

// ---------------------------------------------------------------------------
// ASCC continuous conv:
//   1) count edges per receiver            (atomicAdd histogram)
//   2) exclusive scan -> CSR offsets       (single-CTA scan, n=50000)
//   3) scatter per-edge records (sender, 4 packed taps, 4 win-folded weights)
//   4) fused kernel: per 32-node tile, accumulate A[32][16*64] in SMEM from
//      CSR edge lists (warp-per-node, lane-per-channel-pair), then contract
//      with antisymmetrized kernel K[1024][64] streamed through SMEM.
// ---------------------------------------------------------------------------

#define NMAX   50048
#define EMAX   800000
#define INC    64
#define OUTC   64
#define TAPS   16
#define MTILE  32
#define APAD   1032   // 1024 + 8 floats: breaks the m-stride bank collision
#define SMEM_BYTES ((MTILE*APAD + 64*OUTC) * 4)

struct __align__(16) EdgeRec {
    float4 w;       // bilinear weights * window
    int    sender;
    int    taps;    // 4 x 8-bit tap indices
    int    pad0, pad1;
};

__device__ EdgeRec g_records[EMAX];
__device__ int     g_count  [NMAX];
__device__ int     g_offsets[NMAX + 1];
__device__ int     g_cursor [NMAX];

// ---------------------------------------------------------------------------
__global__ void zero_counts(int n) {
    int i = blockIdx.x * blockDim.x + threadIdx.x;
    if (i < n) g_count[i] = 0;
}

__global__ void count_edges(const int* __restrict__ receivers, int e) {
    int i = blockIdx.x * blockDim.x + threadIdx.x;
    if (i < e) atomicAdd(&g_count[receivers[i]], 1);
}

// single-CTA exclusive scan over g_count -> g_offsets, g_cursor
__global__ void scan_counts(int n) {
    __shared__ int wsum[32];
    int tid = threadIdx.x, lane = tid & 31, wid = tid >> 5;
    int carry = 0;
    for (int base = 0; base < n; base += 1024) {
        int i = base + tid;
        int v = (i < n) ? g_count[i] : 0;
        int x = v;
        #pragma unroll
        for (int d = 1; d < 32; d <<= 1) {
            int y = __shfl_up_sync(0xFFFFFFFFu, x, d);
            if (lane >= d) x += y;
        }
        if (lane == 31) wsum[wid] = x;
        __syncthreads();
        if (wid == 0) {
            int s = wsum[lane];
            #pragma unroll
            for (int d = 1; d < 32; d <<= 1) {
                int y = __shfl_up_sync(0xFFFFFFFFu, s, d);
                if (lane >= d) s += y;
            }
            wsum[lane] = s;
        }
        __syncthreads();
        int excl = carry + (wid ? wsum[wid - 1] : 0) + (x - v);
        if (i < n) { g_offsets[i] = excl; g_cursor[i] = excl; }
        carry += wsum[31];
        __syncthreads();   // protect wsum before next iteration's writes
    }
    if (tid == 0) g_offsets[n] = carry;
}

// ---------------------------------------------------------------------------
__global__ void build_records(const int*   __restrict__ receivers,
                              const int*   __restrict__ senders,
                              const float* __restrict__ relpos,
                              const float* __restrict__ wsp,
                              int e) {
    int i = blockIdx.x * blockDim.x + threadIdx.x;
    if (i >= e) return;
    float ws = wsp[0];
    float rx = relpos[2 * i], ry = relpos[2 * i + 1];
    float ux = fminf(fmaxf(rx / ws, -1.0f), 1.0f);
    float uy = fminf(fmaxf(ry / ws, -1.0f), 1.0f);
    float gx = (ux + 1.0f) * 1.5f;   // 0.5*(kh-1), kh=4
    float gy = (uy + 1.0f) * 1.5f;   // 0.5*(kw-1), kw=4
    float x0f = fminf(fmaxf(floorf(gx), 0.0f), 2.0f);
    float y0f = fminf(fmaxf(floorf(gy), 0.0f), 2.0f);
    float fx = gx - x0f, fy = gy - y0f;
    float r2 = ux * ux + uy * uy;
    float wm = fmaxf(1.0f - r2, 0.0f);
    float win = wm * wm * wm;
    int x0 = (int)x0f, y0 = (int)y0f;
    int t0 = x0 * 4 + y0;

    EdgeRec rec;
    rec.w = make_float4((1.0f - fx) * (1.0f - fy) * win,
                        (1.0f - fx) * fy          * win,
                        fx          * (1.0f - fy) * win,
                        fx          * fy          * win);
    rec.sender = senders[i];
    rec.taps   = t0 | ((t0 + 1) << 8) | ((t0 + 4) << 16) | ((t0 + 5) << 24);
    rec.pad0 = 0; rec.pad1 = 0;

    int r = receivers[i];
    int slot = atomicAdd(&g_cursor[r], 1);
    g_records[slot] = rec;
}

// ---------------------------------------------------------------------------
// Fused aggregate + contract. 256 threads, 32 nodes per CTA.
// Stage A: warp w owns nodes 4w..4w+3; lane owns channel pair (2*lane, 2*lane+1).
// Stage B: thread (og=tid&15, mg=tid>>4): outputs o=4*og..+3 for nodes 2mg, 2mg+1.
__global__ __launch_bounds__(256, 1)
void fused_conv_kernel(const float* __restrict__ features,
                       const float* __restrict__ kernelW,  // [4][2][64][64]
                       const float* __restrict__ bias,
                       float*       __restrict__ out,
                       int n) {
    extern __shared__ float smem[];
    float* As = smem;                     // MTILE * APAD
    float* Ks = smem + MTILE * APAD;      // 64 * 64

    int tid  = threadIdx.x;
    int lane = tid & 31, wid = tid >> 5;
    int nodeBase = blockIdx.x * MTILE;

    // zero accumulation buffer
    for (int i = tid; i < MTILE * APAD; i += 256) As[i] = 0.0f;
    __syncthreads();

    // -------- Stage A: per-node tap accumulation --------
    for (int j = 0; j < 4; ++j) {
        int m = wid * 4 + j;
        int node = nodeBase + m;
        if (node >= n) break;
        int s = g_offsets[node], eend = g_offsets[node + 1];
        float* Am = As + m * APAD;
        for (int idx = s; idx < eend; ++idx) {
            const EdgeRec& rec = g_records[idx];
            float4 w   = rec.w;           // broadcast within warp
            int sender = rec.sender;
            int taps   = rec.taps;
            float2 f = *reinterpret_cast<const float2*>(
                features + sender * INC + lane * 2);

            int tp; float wt; float2* Ap; float2 av;
            tp = taps & 0xFF;          wt = w.x;
            Ap = reinterpret_cast<float2*>(Am + tp * 64) + lane;
            av = *Ap; av.x += wt * f.x; av.y += wt * f.y; *Ap = av;
            tp = (taps >> 8) & 0xFF;   wt = w.y;
            Ap = reinterpret_cast<float2*>(Am + tp * 64) + lane;
            av = *Ap; av.x += wt * f.x; av.y += wt * f.y; *Ap = av;
            tp = (taps >> 16) & 0xFF;  wt = w.z;
            Ap = reinterpret_cast<float2*>(Am + tp * 64) + lane;
            av = *Ap; av.x += wt * f.x; av.y += wt * f.y; *Ap = av;
            tp = (taps >> 24) & 0xFF;  wt = w.w;
            Ap = reinterpret_cast<float2*>(Am + tp * 64) + lane;
            av = *Ap; av.x += wt * f.x; av.y += wt * f.y; *Ap = av;
        }
    }
    __syncthreads();

    // -------- Stage B: contract with antisymmetrized kernel --------
    int og = tid & 15, mg = tid >> 4;
    int o  = og * 4;
    int m0 = mg * 2, m1 = m0 + 1;
    float4 acc0 = make_float4(0.f, 0.f, 0.f, 0.f);
    float4 acc1 = make_float4(0.f, 0.f, 0.f, 0.f);

    for (int t = 0; t < TAPS; ++t) {
        __syncthreads();
        // load K chunk for tap t with antisymmetrization on the fly
        int tx = t >> 2, ty = t & 3;
        const float* src;
        float sgn;
        if (ty < 2) { src = kernelW + (tx * 2 + ty) * 4096;           sgn =  1.0f; }
        else        { src = kernelW + ((3 - tx) * 2 + (3 - ty)) * 4096; sgn = -1.0f; }
        #pragma unroll
        for (int jj = 0; jj < 16; ++jj) {
            int p = tid + jj * 256;
            Ks[p] = sgn * __ldg(src + p);
        }
        __syncthreads();

        const float* A0 = As + m0 * APAD + t * 64;
        const float* A1 = As + m1 * APAD + t * 64;
        #pragma unroll 16
        for (int kk = 0; kk < 64; ++kk) {
            float4 kv = *reinterpret_cast<const float4*>(Ks + kk * 64 + o);
            float a0 = A0[kk];
            float a1 = A1[kk];
            acc0.x += a0 * kv.x; acc0.y += a0 * kv.y;
            acc0.z += a0 * kv.z; acc0.w += a0 * kv.w;
            acc1.x += a1 * kv.x; acc1.y += a1 * kv.y;
            acc1.z += a1 * kv.z; acc1.w += a1 * kv.w;
        }
    }

    float4 b = *reinterpret_cast<const float4*>(bias + o);
    int node0 = nodeBase + m0;
    int node1 = nodeBase + m1;
    if (node0 < n) {
        float4 r = make_float4(acc0.x + b.x, acc0.y + b.y, acc0.z + b.z, acc0.w + b.w);
        *reinterpret_cast<float4*>(out + node0 * OUTC + o) = r;
    }
    if (node1 < n) {
        float4 r = make_float4(acc1.x + b.x, acc1.y + b.y, acc1.z + b.z, acc1.w + b.w);
        *reinterpret_cast<float4*>(out + node1 * OUTC + o) = r;
    }
}

// ---------------------------------------------------------------------------
extern "C" void kernel_launch(void* const* d_in, const int* in_sizes, int n_in,
                              void* d_out, int out_size) {
    const float* features  = (const float*)d_in[0];
    const int*   receivers = (const int*)  d_in[1];
    const float* relpos    = (const float*)d_in[2];
    const float* wsp       = (const float*)d_in[3];
    const int*   senders   = (const int*)  d_in[4];
    const float* kernelW   = (const float*)d_in[5];
    const float* bias      = (const float*)d_in[6];
    float*       out       = (float*)d_out;

    int n = in_sizes[0] / INC;   // 50000
    int e = in_sizes[1];         // 800000

    cudaFuncSetAttribute(fused_conv_kernel,
                         cudaFuncAttributeMaxDynamicSharedMemorySize, SMEM_BYTES);

    zero_counts  <<<(n + 255) / 256, 256>>>(n);
    count_edges  <<<(e + 255) / 256, 256>>>(receivers, e);
    scan_counts  <<<1, 1024>>>(n);
    build_records<<<(e + 255) / 256, 256>>>(receivers, senders, relpos, wsp, e);

    int blocks = (n + MTILE - 1) / MTILE;
    fused_conv_kernel<<<blocks, 256, SMEM_BYTES>>>(features, kernelW, bias, out, n);
}

// round 3
// speedup vs baseline: 1.1188x; 1.1188x over previous
#include <cuda_runtime.h>

// ---------------------------------------------------------------------------
// ASCC continuous conv, v2:
//   1) histogram + scan -> CSR offsets
//   2) scatter per-edge records (sender, 4 packed taps, win-folded weights)
//   3) precompute antisymmetrized kernel K_full[16][64][64] (one tiny kernel)
//   4) fused kernel, 32 nodes/CTA:
//      Stage A: CSR edge aggregation into smem A[32][16*64] with a 1-deep
//               prefetch pipeline (warp-per-node, lane-per-channel-pair)
//      Stage B: contraction with K streamed per-tap through a double-buffered
//               16KB smem stage; float4 register tiling, 8 accumulators.
// ---------------------------------------------------------------------------

#define NMAX   50048
#define EMAX   800000
#define INC    64
#define OUTC   64
#define TAPS   16
#define MTILE  32
#define APAD   1032   // 1024 + 8 floats: breaks the m-stride bank collision
// smem: A tile + 2 x 16KB K buffers
#define SMEM_BYTES ((MTILE*APAD + 2*4096) * 4)

struct __align__(16) EdgeRec {
    float4 w;       // bilinear weights * window
    int    sender;
    int    taps;    // 4 x 8-bit tap indices
    int    pad0, pad1;
};

__device__ EdgeRec g_records[EMAX];
__device__ int     g_count  [NMAX];
__device__ int     g_offsets[NMAX + 1];
__device__ int     g_cursor [NMAX];
__device__ float   g_kfull  [TAPS * INC * OUTC];   // 256 KB

// ---------------------------------------------------------------------------
__global__ void zero_counts(int n) {
    int i = blockIdx.x * blockDim.x + threadIdx.x;
    if (i < n) g_count[i] = 0;
}

__global__ void count_edges(const int* __restrict__ receivers, int e) {
    int i = blockIdx.x * blockDim.x + threadIdx.x;
    if (i < e) atomicAdd(&g_count[receivers[i]], 1);
}

// single-CTA exclusive scan over g_count -> g_offsets, g_cursor
__global__ void scan_counts(int n) {
    __shared__ int wsum[32];
    int tid = threadIdx.x, lane = tid & 31, wid = tid >> 5;
    int carry = 0;
    for (int base = 0; base < n; base += 1024) {
        int i = base + tid;
        int v = (i < n) ? g_count[i] : 0;
        int x = v;
        #pragma unroll
        for (int d = 1; d < 32; d <<= 1) {
            int y = __shfl_up_sync(0xFFFFFFFFu, x, d);
            if (lane >= d) x += y;
        }
        if (lane == 31) wsum[wid] = x;
        __syncthreads();
        if (wid == 0) {
            int s = wsum[lane];
            #pragma unroll
            for (int d = 1; d < 32; d <<= 1) {
                int y = __shfl_up_sync(0xFFFFFFFFu, s, d);
                if (lane >= d) s += y;
            }
            wsum[lane] = s;
        }
        __syncthreads();
        int excl = carry + (wid ? wsum[wid - 1] : 0) + (x - v);
        if (i < n) { g_offsets[i] = excl; g_cursor[i] = excl; }
        carry += wsum[31];
        __syncthreads();
    }
    if (tid == 0) g_offsets[n] = carry;
}

// ---------------------------------------------------------------------------
__global__ void build_records(const int*   __restrict__ receivers,
                              const int*   __restrict__ senders,
                              const float* __restrict__ relpos,
                              const float* __restrict__ wsp,
                              int e) {
    int i = blockIdx.x * blockDim.x + threadIdx.x;
    if (i >= e) return;
    float ws = wsp[0];
    float rx = relpos[2 * i], ry = relpos[2 * i + 1];
    float ux = fminf(fmaxf(rx / ws, -1.0f), 1.0f);
    float uy = fminf(fmaxf(ry / ws, -1.0f), 1.0f);
    float gx = (ux + 1.0f) * 1.5f;
    float gy = (uy + 1.0f) * 1.5f;
    float x0f = fminf(fmaxf(floorf(gx), 0.0f), 2.0f);
    float y0f = fminf(fmaxf(floorf(gy), 0.0f), 2.0f);
    float fx = gx - x0f, fy = gy - y0f;
    float r2 = ux * ux + uy * uy;
    float wm = fmaxf(1.0f - r2, 0.0f);
    float win = wm * wm * wm;
    int x0 = (int)x0f, y0 = (int)y0f;
    int t0 = x0 * 4 + y0;

    EdgeRec rec;
    rec.w = make_float4((1.0f - fx) * (1.0f - fy) * win,
                        (1.0f - fx) * fy          * win,
                        fx          * (1.0f - fy) * win,
                        fx          * fy          * win);
    rec.sender = senders[i];
    rec.taps   = t0 | ((t0 + 1) << 8) | ((t0 + 4) << 16) | ((t0 + 5) << 24);
    rec.pad0 = 0; rec.pad1 = 0;

    int r = receivers[i];
    int slot = atomicAdd(&g_cursor[r], 1);
    g_records[slot] = rec;
}

// ---------------------------------------------------------------------------
// antisymmetrize: full[tx][ty] = ty<2 ? k[tx][ty] : -k[3-tx][3-ty]
__global__ void build_kfull(const float* __restrict__ kernelW) {
    int i = blockIdx.x * blockDim.x + threadIdx.x;   // over 65536
    if (i >= TAPS * 4096) return;
    int t   = i >> 12;
    int rem = i & 4095;
    int tx = t >> 2, ty = t & 3;
    float v;
    if (ty < 2) v =  kernelW[(tx * 2 + ty) * 4096 + rem];
    else        v = -kernelW[((3 - tx) * 2 + (3 - ty)) * 4096 + rem];
    g_kfull[i] = v;
}

// ---------------------------------------------------------------------------
__global__ __launch_bounds__(256, 1)
void fused_conv_kernel(const float* __restrict__ features,
                       const float* __restrict__ bias,
                       float*       __restrict__ out,
                       int n) {
    extern __shared__ float smem[];
    float* As = smem;                     // MTILE * APAD
    float* Ks = smem + MTILE * APAD;      // 2 * 4096

    int tid  = threadIdx.x;
    int lane = tid & 31, wid = tid >> 5;
    int nodeBase = blockIdx.x * MTILE;

    // zero accumulation buffer + preload K tap 0 into buffer 0
    for (int i = tid; i < MTILE * APAD; i += 256) As[i] = 0.0f;
    {
        const float4* src = (const float4*)g_kfull;
        float4 p0 = src[tid], p1 = src[tid + 256],
               p2 = src[tid + 512], p3 = src[tid + 768];
        float4* dst = (float4*)Ks;
        dst[tid] = p0; dst[tid + 256] = p1;
        dst[tid + 512] = p2; dst[tid + 768] = p3;
    }
    __syncthreads();

    // -------- Stage A: per-node tap accumulation with 1-deep prefetch -------
    for (int j = 0; j < 4; ++j) {
        int m = wid * 4 + j;
        int node = nodeBase + m;
        if (node >= n) break;
        int s = g_offsets[node], e2 = g_offsets[node + 1];
        if (s >= e2) continue;
        float* Am = As + m * APAD;

        float4 w4 = g_records[s].w;
        int2 meta = *(const int2*)&g_records[s].sender;
        float2 f  = *(const float2*)(features + (size_t)meta.x * INC + lane * 2);

        for (int idx = s; idx < e2; ++idx) {
            float4 wn = w4; int2 mn = meta; float2 fn = f;
            if (idx + 1 < e2) {
                wn = g_records[idx + 1].w;
                mn = *(const int2*)&g_records[idx + 1].sender;
                fn = *(const float2*)(features + (size_t)mn.x * INC + lane * 2);
            }
            int taps = meta.y;
            float* p; float2 v;
            p = Am + (taps & 0xFF) * 64 + lane * 2;
            v = *(float2*)p; v.x += w4.x * f.x; v.y += w4.x * f.y; *(float2*)p = v;
            p = Am + ((taps >> 8) & 0xFF) * 64 + lane * 2;
            v = *(float2*)p; v.x += w4.y * f.x; v.y += w4.y * f.y; *(float2*)p = v;
            p = Am + ((taps >> 16) & 0xFF) * 64 + lane * 2;
            v = *(float2*)p; v.x += w4.z * f.x; v.y += w4.z * f.y; *(float2*)p = v;
            p = Am + ((taps >> 24) & 0xFF) * 64 + lane * 2;
            v = *(float2*)p; v.x += w4.w * f.x; v.y += w4.w * f.y; *(float2*)p = v;
            w4 = wn; meta = mn; f = fn;
        }
    }
    __syncthreads();

    // -------- Stage B: contract with K (double-buffered per-tap stream) -----
    int og = tid & 15, mg = tid >> 4;
    int o  = og * 4;
    int m0 = mg * 2;
    float4 acc0 = make_float4(0.f, 0.f, 0.f, 0.f);
    float4 acc1 = make_float4(0.f, 0.f, 0.f, 0.f);

    int cur = 0;
    for (int t = 0; t < TAPS; ++t) {
        // prefetch next tap into registers (overlaps with compute below)
        float4 nk0, nk1, nk2, nk3;
        if (t + 1 < TAPS) {
            const float4* src = (const float4*)(g_kfull + (t + 1) * 4096);
            nk0 = src[tid];       nk1 = src[tid + 256];
            nk2 = src[tid + 512]; nk3 = src[tid + 768];
        }

        const float* Kc = Ks + cur * 4096;
        const float* A0 = As + m0 * APAD + t * 64;
        const float* A1 = A0 + APAD;

        #pragma unroll
        for (int kk = 0; kk < 64; kk += 4) {
            float4 a0 = *(const float4*)(A0 + kk);
            float4 a1 = *(const float4*)(A1 + kk);
            float4 k0 = *(const float4*)(Kc + (kk + 0) * 64 + o);
            float4 k1 = *(const float4*)(Kc + (kk + 1) * 64 + o);
            float4 k2 = *(const float4*)(Kc + (kk + 2) * 64 + o);
            float4 k3 = *(const float4*)(Kc + (kk + 3) * 64 + o);

            acc0.x += a0.x * k0.x; acc0.y += a0.x * k0.y;
            acc0.z += a0.x * k0.z; acc0.w += a0.x * k0.w;
            acc1.x += a1.x * k0.x; acc1.y += a1.x * k0.y;
            acc1.z += a1.x * k0.z; acc1.w += a1.x * k0.w;

            acc0.x += a0.y * k1.x; acc0.y += a0.y * k1.y;
            acc0.z += a0.y * k1.z; acc0.w += a0.y * k1.w;
            acc1.x += a1.y * k1.x; acc1.y += a1.y * k1.y;
            acc1.z += a1.y * k1.z; acc1.w += a1.y * k1.w;

            acc0.x += a0.z * k2.x; acc0.y += a0.z * k2.y;
            acc0.z += a0.z * k2.z; acc0.w += a0.z * k2.w;
            acc1.x += a1.z * k2.x; acc1.y += a1.z * k2.y;
            acc1.z += a1.z * k2.z; acc1.w += a1.z * k2.w;

            acc0.x += a0.w * k3.x; acc0.y += a0.w * k3.y;
            acc0.z += a0.w * k3.z; acc0.w += a0.w * k3.w;
            acc1.x += a1.w * k3.x; acc1.y += a1.w * k3.y;
            acc1.z += a1.w * k3.z; acc1.w += a1.w * k3.w;
        }

        // store prefetched tap into the other buffer (no one reads it now)
        if (t + 1 < TAPS) {
            float4* dst = (float4*)(Ks + (cur ^ 1) * 4096);
            dst[tid] = nk0;       dst[tid + 256] = nk1;
            dst[tid + 512] = nk2; dst[tid + 768] = nk3;
        }
        cur ^= 1;
        __syncthreads();   // STS visible before next tap's compute
    }

    float4 b = *reinterpret_cast<const float4*>(bias + o);
    int node0 = nodeBase + m0;
    int node1 = node0 + 1;
    if (node0 < n) {
        float4 r = make_float4(acc0.x + b.x, acc0.y + b.y,
                               acc0.z + b.z, acc0.w + b.w);
        *reinterpret_cast<float4*>(out + (size_t)node0 * OUTC + o) = r;
    }
    if (node1 < n) {
        float4 r = make_float4(acc1.x + b.x, acc1.y + b.y,
                               acc1.z + b.z, acc1.w + b.w);
        *reinterpret_cast<float4*>(out + (size_t)node1 * OUTC + o) = r;
    }
}

// ---------------------------------------------------------------------------
extern "C" void kernel_launch(void* const* d_in, const int* in_sizes, int n_in,
                              void* d_out, int out_size) {
    const float* features  = (const float*)d_in[0];
    const int*   receivers = (const int*)  d_in[1];
    const float* relpos    = (const float*)d_in[2];
    const float* wsp       = (const float*)d_in[3];
    const int*   senders   = (const int*)  d_in[4];
    const float* kernelW   = (const float*)d_in[5];
    const float* bias      = (const float*)d_in[6];
    float*       out       = (float*)d_out;

    int n = in_sizes[0] / INC;   // 50000
    int e = in_sizes[1];         // 800000

    cudaFuncSetAttribute(fused_conv_kernel,
                         cudaFuncAttributeMaxDynamicSharedMemorySize, SMEM_BYTES);

    zero_counts  <<<(n + 255) / 256, 256>>>(n);
    count_edges  <<<(e + 255) / 256, 256>>>(receivers, e);
    scan_counts  <<<1, 1024>>>(n);
    build_records<<<(e + 255) / 256, 256>>>(receivers, senders, relpos, wsp, e);
    build_kfull  <<<(TAPS * 4096 + 255) / 256, 256>>>(kernelW);

    int blocks = (n + MTILE - 1) / MTILE;
    fused_conv_kernel<<<blocks, 256, SMEM_BYTES>>>(features, bias, out, n);
}

// round 4
// speedup vs baseline: 1.5339x; 1.3710x over previous
#include <cuda_runtime.h>
#include <cuda_bf16.h>

// ---------------------------------------------------------------------------
// ASCC continuous conv, v3 (tensor-core stage B):
//   1) histogram + scan -> CSR offsets
//   2) scatter per-edge records
//   3) build K in mma-canonical split-bf16 fragment layout (hi/lo)
//   4) fused kernel, 32 nodes/CTA:
//      Stage A: CSR aggregation into smem A[32][1024] fp32 (warp-per-node)
//      Conv:    in-place fp32 -> packed (bf16_hi, bf16_lo) word pairs
//      Stage B: mma.sync.m16n8k16 bf16, 3-product split precision,
//               K fragments streamed from L2 with 1-deep prefetch.
// ---------------------------------------------------------------------------

#define NMAX   50048
#define EMAX   800000
#define INC    64
#define OUTC   64
#define TAPS   16
#define MTILE  32
#define APAD   1034   // even (float2 align), 1034%32=10 spreads row banks
#define SMEM_BYTES (MTILE * APAD * 4)

#define KSLICES 64    // 1024 / 16
#define NTILES  8     // 64 / 8

struct __align__(16) EdgeRec {
    float4 w;
    int    sender;
    int    taps;
    int    pad0, pad1;
};

__device__ EdgeRec g_records[EMAX];
__device__ int     g_count  [NMAX];
__device__ int     g_offsets[NMAX + 1];
__device__ int     g_cursor [NMAX];
// K fragments, canonical m16n8k16 B layout: [slice][ntile][lane] -> uint2
__device__ uint2   g_kc_hi[KSLICES * NTILES * 32];
__device__ uint2   g_kc_lo[KSLICES * NTILES * 32];

// ---------------------------------------------------------------------------
__global__ void zero_counts(int n) {
    int i = blockIdx.x * blockDim.x + threadIdx.x;
    if (i < n) g_count[i] = 0;
}

__global__ void count_edges(const int* __restrict__ receivers, int e) {
    int i = blockIdx.x * blockDim.x + threadIdx.x;
    if (i < e) atomicAdd(&g_count[receivers[i]], 1);
}

__global__ void scan_counts(int n) {
    __shared__ int wsum[32];
    int tid = threadIdx.x, lane = tid & 31, wid = tid >> 5;
    int carry = 0;
    for (int base = 0; base < n; base += 1024) {
        int i = base + tid;
        int v = (i < n) ? g_count[i] : 0;
        int x = v;
        #pragma unroll
        for (int d = 1; d < 32; d <<= 1) {
            int y = __shfl_up_sync(0xFFFFFFFFu, x, d);
            if (lane >= d) x += y;
        }
        if (lane == 31) wsum[wid] = x;
        __syncthreads();
        if (wid == 0) {
            int s = wsum[lane];
            #pragma unroll
            for (int d = 1; d < 32; d <<= 1) {
                int y = __shfl_up_sync(0xFFFFFFFFu, s, d);
                if (lane >= d) s += y;
            }
            wsum[lane] = s;
        }
        __syncthreads();
        int excl = carry + (wid ? wsum[wid - 1] : 0) + (x - v);
        if (i < n) { g_offsets[i] = excl; g_cursor[i] = excl; }
        carry += wsum[31];
        __syncthreads();
    }
    if (tid == 0) g_offsets[n] = carry;
}

// ---------------------------------------------------------------------------
__global__ void build_records(const int*   __restrict__ receivers,
                              const int*   __restrict__ senders,
                              const float* __restrict__ relpos,
                              const float* __restrict__ wsp,
                              int e) {
    int i = blockIdx.x * blockDim.x + threadIdx.x;
    if (i >= e) return;
    float ws = wsp[0];
    float rx = relpos[2 * i], ry = relpos[2 * i + 1];
    float ux = fminf(fmaxf(rx / ws, -1.0f), 1.0f);
    float uy = fminf(fmaxf(ry / ws, -1.0f), 1.0f);
    float gx = (ux + 1.0f) * 1.5f;
    float gy = (uy + 1.0f) * 1.5f;
    float x0f = fminf(fmaxf(floorf(gx), 0.0f), 2.0f);
    float y0f = fminf(fmaxf(floorf(gy), 0.0f), 2.0f);
    float fx = gx - x0f, fy = gy - y0f;
    float r2 = ux * ux + uy * uy;
    float wm = fmaxf(1.0f - r2, 0.0f);
    float win = wm * wm * wm;
    int x0 = (int)x0f, y0 = (int)y0f;
    int t0 = x0 * 4 + y0;

    EdgeRec rec;
    rec.w = make_float4((1.0f - fx) * (1.0f - fy) * win,
                        (1.0f - fx) * fy          * win,
                        fx          * (1.0f - fy) * win,
                        fx          * fy          * win);
    rec.sender = senders[i];
    rec.taps   = t0 | ((t0 + 1) << 8) | ((t0 + 4) << 16) | ((t0 + 5) << 24);
    rec.pad0 = 0; rec.pad1 = 0;

    int r = receivers[i];
    int slot = atomicAdd(&g_cursor[r], 1);
    g_records[slot] = rec;
}

// ---------------------------------------------------------------------------
// antisymmetrized K value at (global k index, out channel n)
__device__ __forceinline__ float kfull_val(const float* __restrict__ kernelW,
                                           int k, int nn) {
    int tap = k >> 6, i = k & 63;
    int tx = tap >> 2, ty = tap & 3;
    if (ty < 2) return  kernelW[(tx * 2 + ty) * 4096 + i * 64 + nn];
    else        return -kernelW[((3 - tx) * 2 + (3 - ty)) * 4096 + i * 64 + nn];
}

// canonical B fragments for m16n8k16 bf16 (row.col): thread (g=lane>>2,c=lane&3)
// b0 = K[k=16s+2c, 16s+2c+1][n], b1 = K[k+8, k+9][n], n = nt*8 + g
__global__ void build_kcanon(const float* __restrict__ kernelW) {
    int idx = blockIdx.x * blockDim.x + threadIdx.x;   // 0 .. 16383
    if (idx >= KSLICES * NTILES * 32) return;
    int lane = idx & 31;
    int nt   = (idx >> 5) & 7;
    int s    = idx >> 8;
    int g = lane >> 2, c = lane & 3;
    int nn = nt * 8 + g;
    int k0 = s * 16 + 2 * c;

    float v0 = kfull_val(kernelW, k0,     nn);
    float v1 = kfull_val(kernelW, k0 + 1, nn);
    float v2 = kfull_val(kernelW, k0 + 8, nn);
    float v3 = kfull_val(kernelW, k0 + 9, nn);

    __nv_bfloat162 h01 = __floats2bfloat162_rn(v0, v1);
    __nv_bfloat162 h23 = __floats2bfloat162_rn(v2, v3);
    float h0 = __bfloat162float(__low2bfloat16(h01));
    float h1 = __bfloat162float(__high2bfloat16(h01));
    float h2 = __bfloat162float(__low2bfloat16(h23));
    float h3 = __bfloat162float(__high2bfloat16(h23));
    __nv_bfloat162 l01 = __floats2bfloat162_rn(v0 - h0, v1 - h1);
    __nv_bfloat162 l23 = __floats2bfloat162_rn(v2 - h2, v3 - h3);

    uint2 hi, lo;
    hi.x = *reinterpret_cast<unsigned*>(&h01);
    hi.y = *reinterpret_cast<unsigned*>(&h23);
    lo.x = *reinterpret_cast<unsigned*>(&l01);
    lo.y = *reinterpret_cast<unsigned*>(&l23);
    g_kc_hi[idx] = hi;
    g_kc_lo[idx] = lo;
}

// ---------------------------------------------------------------------------
__device__ __forceinline__ void mma16816(float* d,
        unsigned a0, unsigned a1, unsigned a2, unsigned a3,
        unsigned b0, unsigned b1) {
    asm volatile(
        "mma.sync.aligned.m16n8k16.row.col.f32.bf16.bf16.f32 "
        "{%0,%1,%2,%3}, {%4,%5,%6,%7}, {%8,%9}, {%0,%1,%2,%3};"
        : "+f"(d[0]), "+f"(d[1]), "+f"(d[2]), "+f"(d[3])
        : "r"(a0), "r"(a1), "r"(a2), "r"(a3), "r"(b0), "r"(b1));
}

__global__ __launch_bounds__(256, 1)
void fused_conv_kernel(const float* __restrict__ features,
                       const float* __restrict__ bias,
                       float*       __restrict__ out,
                       int n) {
    extern __shared__ float smem[];
    float* As = smem;   // MTILE * APAD fp32, later reinterpreted as word pairs

    int tid  = threadIdx.x;
    int lane = tid & 31, wid = tid >> 5;
    int nodeBase = blockIdx.x * MTILE;

    for (int i = tid; i < MTILE * APAD; i += 256) As[i] = 0.0f;
    __syncthreads();

    // -------- Stage A: per-node tap accumulation with 1-deep prefetch -------
    for (int j = 0; j < 4; ++j) {
        int m = wid * 4 + j;
        int node = nodeBase + m;
        if (node >= n) break;
        int s = g_offsets[node], e2 = g_offsets[node + 1];
        if (s >= e2) continue;
        float* Am = As + m * APAD;

        float4 w4 = g_records[s].w;
        int2 meta = *(const int2*)&g_records[s].sender;
        float2 f  = *(const float2*)(features + (size_t)meta.x * INC + lane * 2);

        for (int idx = s; idx < e2; ++idx) {
            float4 wn = w4; int2 mn = meta; float2 fn = f;
            if (idx + 1 < e2) {
                wn = g_records[idx + 1].w;
                mn = *(const int2*)&g_records[idx + 1].sender;
                fn = *(const float2*)(features + (size_t)mn.x * INC + lane * 2);
            }
            int taps = meta.y;
            float* p; float2 v;
            p = Am + (taps & 0xFF) * 64 + lane * 2;
            v = *(float2*)p; v.x += w4.x * f.x; v.y += w4.x * f.y; *(float2*)p = v;
            p = Am + ((taps >> 8) & 0xFF) * 64 + lane * 2;
            v = *(float2*)p; v.x += w4.y * f.x; v.y += w4.y * f.y; *(float2*)p = v;
            p = Am + ((taps >> 16) & 0xFF) * 64 + lane * 2;
            v = *(float2*)p; v.x += w4.z * f.x; v.y += w4.z * f.y; *(float2*)p = v;
            p = Am + ((taps >> 24) & 0xFF) * 64 + lane * 2;
            v = *(float2*)p; v.x += w4.w * f.x; v.y += w4.w * f.y; *(float2*)p = v;
            w4 = wn; meta = mn; f = fn;
        }
    }
    __syncthreads();

    // -------- Convert A in place: fp32 pair -> (hi bf16x2, lo bf16x2) -------
    // word(m, pair j): offset m*APAD + 2j  -> {hi, lo}
    for (int i = tid; i < MTILE * 512; i += 256) {
        int m = i >> 9;
        int j = i & 511;
        float* p = As + m * APAD + 2 * j;
        float2 v = *(float2*)p;
        __nv_bfloat162 h2 = __floats2bfloat162_rn(v.x, v.y);
        float h0 = __bfloat162float(__low2bfloat16(h2));
        float h1 = __bfloat162float(__high2bfloat16(h2));
        __nv_bfloat162 l2 = __floats2bfloat162_rn(v.x - h0, v.y - h1);
        uint2 w;
        w.x = *reinterpret_cast<unsigned*>(&h2);
        w.y = *reinterpret_cast<unsigned*>(&l2);
        *(uint2*)p = w;
    }
    __syncthreads();

    // -------- Stage B: split-bf16 tensor-core contraction --------
    // warp -> (mtile = wid&1, npair = wid>>1 covering ntiles 2*npair, 2*npair+1)
    int mtile = wid & 1, npair = wid >> 1;
    int g = lane >> 2, c = lane & 3;
    const float* rowA  = As + (mtile * 16 + g) * APAD;
    const float* rowA8 = rowA + 8 * APAD;
    int nt0 = npair * 2, nt1 = nt0 + 1;

    float d0[4] = {0.f, 0.f, 0.f, 0.f};
    float d1[4] = {0.f, 0.f, 0.f, 0.f};

    uint2 kh0 = g_kc_hi[(0 * NTILES + nt0) * 32 + lane];
    uint2 kl0 = g_kc_lo[(0 * NTILES + nt0) * 32 + lane];
    uint2 kh1 = g_kc_hi[(0 * NTILES + nt1) * 32 + lane];
    uint2 kl1 = g_kc_lo[(0 * NTILES + nt1) * 32 + lane];

    #pragma unroll 4
    for (int s = 0; s < KSLICES; ++s) {
        uint2 nh0, nl0, nh1, nl1;
        if (s + 1 < KSLICES) {
            int b = (s + 1) * NTILES;
            nh0 = g_kc_hi[(b + nt0) * 32 + lane];
            nl0 = g_kc_lo[(b + nt0) * 32 + lane];
            nh1 = g_kc_hi[(b + nt1) * 32 + lane];
            nl1 = g_kc_lo[(b + nt1) * 32 + lane];
        }
        const float* pa = rowA  + 16 * s + 2 * c;
        const float* pb = rowA8 + 16 * s + 2 * c;
        uint2 A0 = *(const uint2*)(pa);
        uint2 A1 = *(const uint2*)(pb);
        uint2 A2 = *(const uint2*)(pa + 8);
        uint2 A3 = *(const uint2*)(pb + 8);

        // D += Ahi*Khi + Ahi*Klo + Alo*Khi
        mma16816(d0, A0.x, A1.x, A2.x, A3.x, kh0.x, kh0.y);
        mma16816(d0, A0.x, A1.x, A2.x, A3.x, kl0.x, kl0.y);
        mma16816(d0, A0.y, A1.y, A2.y, A3.y, kh0.x, kh0.y);
        mma16816(d1, A0.x, A1.x, A2.x, A3.x, kh1.x, kh1.y);
        mma16816(d1, A0.x, A1.x, A2.x, A3.x, kl1.x, kl1.y);
        mma16816(d1, A0.y, A1.y, A2.y, A3.y, kh1.x, kh1.y);

        kh0 = nh0; kl0 = nl0; kh1 = nh1; kl1 = nl1;
    }

    // -------- store D + bias --------
    int node0 = nodeBase + mtile * 16 + g;
    int node8 = node0 + 8;
    {
        int o = nt0 * 8 + 2 * c;
        float2 b = *(const float2*)(bias + o);
        if (node0 < n) {
            float2 r = make_float2(d0[0] + b.x, d0[1] + b.y);
            *(float2*)(out + (size_t)node0 * OUTC + o) = r;
        }
        if (node8 < n) {
            float2 r = make_float2(d0[2] + b.x, d0[3] + b.y);
            *(float2*)(out + (size_t)node8 * OUTC + o) = r;
        }
    }
    {
        int o = nt1 * 8 + 2 * c;
        float2 b = *(const float2*)(bias + o);
        if (node0 < n) {
            float2 r = make_float2(d1[0] + b.x, d1[1] + b.y);
            *(float2*)(out + (size_t)node0 * OUTC + o) = r;
        }
        if (node8 < n) {
            float2 r = make_float2(d1[2] + b.x, d1[3] + b.y);
            *(float2*)(out + (size_t)node8 * OUTC + o) = r;
        }
    }
}

// ---------------------------------------------------------------------------
extern "C" void kernel_launch(void* const* d_in, const int* in_sizes, int n_in,
                              void* d_out, int out_size) {
    const float* features  = (const float*)d_in[0];
    const int*   receivers = (const int*)  d_in[1];
    const float* relpos    = (const float*)d_in[2];
    const float* wsp       = (const float*)d_in[3];
    const int*   senders   = (const int*)  d_in[4];
    const float* kernelW   = (const float*)d_in[5];
    const float* bias      = (const float*)d_in[6];
    float*       out       = (float*)d_out;

    int n = in_sizes[0] / INC;   // 50000
    int e = in_sizes[1];         // 800000

    cudaFuncSetAttribute(fused_conv_kernel,
                         cudaFuncAttributeMaxDynamicSharedMemorySize, SMEM_BYTES);

    zero_counts  <<<(n + 255) / 256, 256>>>(n);
    count_edges  <<<(e + 255) / 256, 256>>>(receivers, e);
    scan_counts  <<<1, 1024>>>(n);
    build_records<<<(e + 255) / 256, 256>>>(receivers, senders, relpos, wsp, e);
    build_kcanon <<<(KSLICES * NTILES * 32 + 255) / 256, 256>>>(kernelW);

    int blocks = (n + MTILE - 1) / MTILE;
    fused_conv_kernel<<<blocks, 256, SMEM_BYTES>>>(features, bias, out, n);
}

// round 5
// speedup vs baseline: 2.2234x; 1.4495x over previous
#include <cuda_runtime.h>
#include <cuda_bf16.h>

// ---------------------------------------------------------------------------
// ASCC continuous conv, v4:
//   - CSR sort (histogram + scan + scatter), SoA edge records (w4 + meta)
//   - K in mma-canonical split-bf16 uint4 fragments (hi.x,hi.y,lo.x,lo.y)
//   - fused kernel, 16 nodes/CTA, 2 CTAs/SM:
//     Stage A: CTA-contiguous edge range staged through smem in 512-edge
//              chunks (bulk cooperative load); warp-per-2-adjacent-nodes;
//              depth-8 register pipeline on the feature gather.
//     Conv:    fp32 -> packed (bf16 hi, bf16 lo) in place
//     Stage B: m16n8k16 bf16 x3 (split precision), K prefetch depth 4.
// ---------------------------------------------------------------------------

#define NMAX    50048
#define EMAX    800000
#define INC     64
#define OUTC    64
#define MTILE   16
#define APAD    1032            // stride % 32 == 8 -> 2-phase LDS.64 floor
#define CHUNK   512
#define FDEPTH  8

#define KSLICES 64              // 1024 / 16
#define NTILES  8               // 64 / 8

// smem: A tile + staged w4 + staged meta
#define SMEM_FLOATS (MTILE * APAD)
#define SMEM_BYTES  (SMEM_FLOATS * 4 + CHUNK * 16 + CHUNK * 8)

__device__ float4 g_w   [EMAX];
__device__ int2   g_meta[EMAX];
__device__ int    g_count  [NMAX];
__device__ int    g_offsets[NMAX + 1];
__device__ int    g_cursor [NMAX];
__device__ uint4  g_kc[KSLICES * NTILES * 32];   // {hi.x, hi.y, lo.x, lo.y}

// ---------------------------------------------------------------------------
__global__ void zero_counts(int n) {
    int i = blockIdx.x * blockDim.x + threadIdx.x;
    if (i < n) g_count[i] = 0;
}

__global__ void count_edges(const int* __restrict__ receivers, int e) {
    int i = blockIdx.x * blockDim.x + threadIdx.x;
    if (i < e) atomicAdd(&g_count[receivers[i]], 1);
}

__global__ void scan_counts(int n) {
    __shared__ int wsum[32];
    int tid = threadIdx.x, lane = tid & 31, wid = tid >> 5;
    int carry = 0;
    for (int base = 0; base < n; base += 1024) {
        int i = base + tid;
        int v = (i < n) ? g_count[i] : 0;
        int x = v;
        #pragma unroll
        for (int d = 1; d < 32; d <<= 1) {
            int y = __shfl_up_sync(0xFFFFFFFFu, x, d);
            if (lane >= d) x += y;
        }
        if (lane == 31) wsum[wid] = x;
        __syncthreads();
        if (wid == 0) {
            int s = wsum[lane];
            #pragma unroll
            for (int d = 1; d < 32; d <<= 1) {
                int y = __shfl_up_sync(0xFFFFFFFFu, s, d);
                if (lane >= d) s += y;
            }
            wsum[lane] = s;
        }
        __syncthreads();
        int excl = carry + (wid ? wsum[wid - 1] : 0) + (x - v);
        if (i < n) { g_offsets[i] = excl; g_cursor[i] = excl; }
        carry += wsum[31];
        __syncthreads();
    }
    if (tid == 0) g_offsets[n] = carry;
}

// ---------------------------------------------------------------------------
__global__ void build_records(const int*   __restrict__ receivers,
                              const int*   __restrict__ senders,
                              const float* __restrict__ relpos,
                              const float* __restrict__ wsp,
                              int e) {
    int i = blockIdx.x * blockDim.x + threadIdx.x;
    if (i >= e) return;
    float ws = wsp[0];
    float rx = relpos[2 * i], ry = relpos[2 * i + 1];
    float ux = fminf(fmaxf(rx / ws, -1.0f), 1.0f);
    float uy = fminf(fmaxf(ry / ws, -1.0f), 1.0f);
    float gx = (ux + 1.0f) * 1.5f;
    float gy = (uy + 1.0f) * 1.5f;
    float x0f = fminf(fmaxf(floorf(gx), 0.0f), 2.0f);
    float y0f = fminf(fmaxf(floorf(gy), 0.0f), 2.0f);
    float fx = gx - x0f, fy = gy - y0f;
    float r2 = ux * ux + uy * uy;
    float wm = fmaxf(1.0f - r2, 0.0f);
    float win = wm * wm * wm;
    int x0 = (int)x0f, y0 = (int)y0f;
    int t0 = x0 * 4 + y0;

    float4 w = make_float4((1.0f - fx) * (1.0f - fy) * win,
                           (1.0f - fx) * fy          * win,
                           fx          * (1.0f - fy) * win,
                           fx          * fy          * win);
    int taps = t0 | ((t0 + 1) << 8) | ((t0 + 4) << 16) | ((t0 + 5) << 24);

    int r = receivers[i];
    int slot = atomicAdd(&g_cursor[r], 1);
    g_w[slot]    = w;
    g_meta[slot] = make_int2(senders[i], taps);
}

// ---------------------------------------------------------------------------
__device__ __forceinline__ float kfull_val(const float* __restrict__ kernelW,
                                           int k, int nn) {
    int tap = k >> 6, i = k & 63;
    int tx = tap >> 2, ty = tap & 3;
    if (ty < 2) return  kernelW[(tx * 2 + ty) * 4096 + i * 64 + nn];
    else        return -kernelW[((3 - tx) * 2 + (3 - ty)) * 4096 + i * 64 + nn];
}

// canonical m16n8k16 B fragments, hi/lo split, packed uint4
__global__ void build_kcanon(const float* __restrict__ kernelW) {
    int idx = blockIdx.x * blockDim.x + threadIdx.x;   // 0 .. 16383
    if (idx >= KSLICES * NTILES * 32) return;
    int lane = idx & 31;
    int nt   = (idx >> 5) & 7;
    int s    = idx >> 8;
    int g = lane >> 2, c = lane & 3;
    int nn = nt * 8 + g;
    int k0 = s * 16 + 2 * c;

    float v0 = kfull_val(kernelW, k0,     nn);
    float v1 = kfull_val(kernelW, k0 + 1, nn);
    float v2 = kfull_val(kernelW, k0 + 8, nn);
    float v3 = kfull_val(kernelW, k0 + 9, nn);

    __nv_bfloat162 h01 = __floats2bfloat162_rn(v0, v1);
    __nv_bfloat162 h23 = __floats2bfloat162_rn(v2, v3);
    float h0 = __bfloat162float(__low2bfloat16(h01));
    float h1 = __bfloat162float(__high2bfloat16(h01));
    float h2 = __bfloat162float(__low2bfloat16(h23));
    float h3 = __bfloat162float(__high2bfloat16(h23));
    __nv_bfloat162 l01 = __floats2bfloat162_rn(v0 - h0, v1 - h1);
    __nv_bfloat162 l23 = __floats2bfloat162_rn(v2 - h2, v3 - h3);

    uint4 kv;
    kv.x = *reinterpret_cast<unsigned*>(&h01);
    kv.y = *reinterpret_cast<unsigned*>(&h23);
    kv.z = *reinterpret_cast<unsigned*>(&l01);
    kv.w = *reinterpret_cast<unsigned*>(&l23);
    g_kc[idx] = kv;
}

// ---------------------------------------------------------------------------
__device__ __forceinline__ void mma16816(float* d,
        unsigned a0, unsigned a1, unsigned a2, unsigned a3,
        unsigned b0, unsigned b1) {
    asm volatile(
        "mma.sync.aligned.m16n8k16.row.col.f32.bf16.bf16.f32 "
        "{%0,%1,%2,%3}, {%4,%5,%6,%7}, {%8,%9}, {%0,%1,%2,%3};"
        : "+f"(d[0]), "+f"(d[1]), "+f"(d[2]), "+f"(d[3])
        : "r"(a0), "r"(a1), "r"(a2), "r"(a3), "r"(b0), "r"(b1));
}

__global__ __launch_bounds__(256, 2)
void fused_conv_kernel(const float* __restrict__ features,
                       const float* __restrict__ bias,
                       float*       __restrict__ out,
                       int n) {
    extern __shared__ float smem[];
    float*  As = smem;                                   // MTILE * APAD
    float4* ws = (float4*)(smem + SMEM_FLOATS);          // CHUNK
    int2*   ms = (int2*)((char*)ws + CHUNK * 16);        // CHUNK

    int tid  = threadIdx.x;
    int lane = tid & 31, wid = tid >> 5;
    int nodeBase = blockIdx.x * MTILE;

    for (int i = tid; i < SMEM_FLOATS; i += 256) As[i] = 0.0f;

    // warp's node pair (adjacent -> contiguous edge range)
    int n0 = min(nodeBase + 2 * wid,     n);
    int n1 = min(nodeBase + 2 * wid + 1, n);
    int n2 = min(nodeBase + 2 * wid + 2, n);
    int s   = g_offsets[n0];
    int mid = g_offsets[n1];
    int e2  = g_offsets[n2];
    float* Am0 = As + (2 * wid) * APAD;
    float* Am1 = Am0 + APAD;

    int o0 = g_offsets[nodeBase];
    int oE = g_offsets[min(nodeBase + MTILE, n)];

    // -------- Stage A: chunked staging + warp-per-node-pair apply --------
    for (int cs = o0; cs < oE; cs += CHUNK) {
        int ce  = min(cs + CHUNK, oE);
        int cnt = ce - cs;
        __syncthreads();                       // previous chunk consumed
        for (int i = tid; i < cnt; i += 256) {
            ws[i] = g_w[cs + i];
            ms[i] = g_meta[cs + i];
        }
        __syncthreads();

        int js = max(s, cs), je = min(e2, ce);
        if (js < je) {
            float2 fbuf[FDEPTH];
            #pragma unroll
            for (int d = 0; d < FDEPTH; ++d) {
                if (js + d < je) {
                    int snd = ms[js + d - cs].x;
                    fbuf[d] = *(const float2*)(features + (size_t)snd * INC + lane * 2);
                }
            }
            for (int jb = js; jb < je; jb += FDEPTH) {
                #pragma unroll
                for (int d = 0; d < FDEPTH; ++d) {
                    int j = jb + d;
                    if (j >= je) break;
                    int li = j - cs;
                    float4 w4  = ws[li];
                    int    tps = ms[li].y;
                    float2 f   = fbuf[d];
                    int jn = j + FDEPTH;
                    if (jn < je) {
                        int snd = ms[jn - cs].x;
                        fbuf[d] = *(const float2*)(features + (size_t)snd * INC + lane * 2);
                    }
                    float* Am = (j < mid) ? Am0 : Am1;
                    float* p; float2 v;
                    p = Am + (tps & 0xFF) * 64 + lane * 2;
                    v = *(float2*)p; v.x += w4.x * f.x; v.y += w4.x * f.y; *(float2*)p = v;
                    p = Am + ((tps >> 8) & 0xFF) * 64 + lane * 2;
                    v = *(float2*)p; v.x += w4.y * f.x; v.y += w4.y * f.y; *(float2*)p = v;
                    p = Am + ((tps >> 16) & 0xFF) * 64 + lane * 2;
                    v = *(float2*)p; v.x += w4.z * f.x; v.y += w4.z * f.y; *(float2*)p = v;
                    p = Am + ((tps >> 24) & 0xFF) * 64 + lane * 2;
                    v = *(float2*)p; v.x += w4.w * f.x; v.y += w4.w * f.y; *(float2*)p = v;
                }
            }
        }
    }
    __syncthreads();

    // -------- Convert A in place: fp32 pair -> (hi bf16x2, lo bf16x2) -------
    for (int i = tid; i < MTILE * 512; i += 256) {
        int m = i >> 9;
        int j = i & 511;
        float* p = As + m * APAD + 2 * j;
        float2 v = *(float2*)p;
        __nv_bfloat162 h2 = __floats2bfloat162_rn(v.x, v.y);
        float h0 = __bfloat162float(__low2bfloat16(h2));
        float h1 = __bfloat162float(__high2bfloat16(h2));
        __nv_bfloat162 l2 = __floats2bfloat162_rn(v.x - h0, v.y - h1);
        uint2 w;
        w.x = *reinterpret_cast<unsigned*>(&h2);
        w.y = *reinterpret_cast<unsigned*>(&l2);
        *(uint2*)p = w;
    }
    __syncthreads();

    // -------- Stage B: split-bf16 tensor-core contraction --------
    // warp wid owns ntile nt = wid (8 output cols); covers all 16 rows.
    int nt = wid;
    int g = lane >> 2, c = lane & 3;
    const float* rowA  = As + g * APAD;
    const float* rowA8 = rowA + 8 * APAD;

    float d0[4] = {0.f, 0.f, 0.f, 0.f};

    uint4 kb[4];
    #pragma unroll
    for (int d = 0; d < 4; ++d)
        kb[d] = g_kc[(d * NTILES + nt) * 32 + lane];

    for (int sb = 0; sb < KSLICES; sb += 4) {
        #pragma unroll
        for (int d = 0; d < 4; ++d) {
            int sl = sb + d;
            uint4 kv = kb[d];
            if (sl + 4 < KSLICES)
                kb[d] = g_kc[((sl + 4) * NTILES + nt) * 32 + lane];
            const float* pa = rowA  + 16 * sl + 2 * c;
            const float* pb = rowA8 + 16 * sl + 2 * c;
            uint2 A0 = *(const uint2*)(pa);
            uint2 A1 = *(const uint2*)(pb);
            uint2 A2 = *(const uint2*)(pa + 8);
            uint2 A3 = *(const uint2*)(pb + 8);
            // D += Ahi*Khi + Ahi*Klo + Alo*Khi
            mma16816(d0, A0.x, A1.x, A2.x, A3.x, kv.x, kv.y);
            mma16816(d0, A0.x, A1.x, A2.x, A3.x, kv.z, kv.w);
            mma16816(d0, A0.y, A1.y, A2.y, A3.y, kv.x, kv.y);
        }
    }

    // -------- store D + bias --------
    int node0 = nodeBase + g;
    int node8 = node0 + 8;
    int o = nt * 8 + 2 * c;
    float2 b = *(const float2*)(bias + o);
    if (node0 < n) {
        float2 r = make_float2(d0[0] + b.x, d0[1] + b.y);
        *(float2*)(out + (size_t)node0 * OUTC + o) = r;
    }
    if (node8 < n) {
        float2 r = make_float2(d0[2] + b.x, d0[3] + b.y);
        *(float2*)(out + (size_t)node8 * OUTC + o) = r;
    }
}

// ---------------------------------------------------------------------------
extern "C" void kernel_launch(void* const* d_in, const int* in_sizes, int n_in,
                              void* d_out, int out_size) {
    const float* features  = (const float*)d_in[0];
    const int*   receivers = (const int*)  d_in[1];
    const float* relpos    = (const float*)d_in[2];
    const float* wsp       = (const float*)d_in[3];
    const int*   senders   = (const int*)  d_in[4];
    const float* kernelW   = (const float*)d_in[5];
    const float* bias      = (const float*)d_in[6];
    float*       out       = (float*)d_out;

    int n = in_sizes[0] / INC;   // 50000
    int e = in_sizes[1];         // 800000

    cudaFuncSetAttribute(fused_conv_kernel,
                         cudaFuncAttributeMaxDynamicSharedMemorySize, SMEM_BYTES);

    zero_counts  <<<(n + 255) / 256, 256>>>(n);
    count_edges  <<<(e + 255) / 256, 256>>>(receivers, e);
    scan_counts  <<<1, 1024>>>(n);
    build_records<<<(e + 255) / 256, 256>>>(receivers, senders, relpos, wsp, e);
    build_kcanon <<<(KSLICES * NTILES * 32 + 255) / 256, 256>>>(kernelW);

    int blocks = (n + MTILE - 1) / MTILE;
    fused_conv_kernel<<<blocks, 256, SMEM_BYTES>>>(features, bias, out, n);
}

// round 6
// speedup vs baseline: 2.7113x; 1.2195x over previous
#include <cuda_runtime.h>
#include <cuda_bf16.h>

// ---------------------------------------------------------------------------
// ASCC continuous conv, v5:
//   - CSR sort (histogram + 3-kernel parallel scan + scatter), SoA records
//   - K in mma-canonical split-bf16 uint4 fragments
//   - fused kernel, 16 nodes/CTA, 2 CTAs/SM:
//     Stage A: register-double-buffered 256-edge chunks (1 edge/thread);
//              per-edge tap RMWs batched load4/fma8/store4 (taps distinct);
//              depth-8 feature-gather pipeline.
//     Conv:    fp32 -> packed (bf16 hi, bf16 lo) in place
//     Stage B: m16n8k16 bf16 x3 split precision, K prefetch depth 4.
// ---------------------------------------------------------------------------

#define NMAX    50048
#define EMAX    800000
#define INC     64
#define OUTC    64
#define MTILE   16
#define APAD    1032            // stride % 32 == 8 -> conflict-free LDS.64
#define CHUNK   256             // one staged edge per thread
#define FDEPTH  8
#define NBMAX   64              // scan blocks (50048/1024 = 49)

#define KSLICES 64              // 1024 / 16
#define NTILES  8               // 64 / 8

#define SMEM_FLOATS (MTILE * APAD)
#define SMEM_BYTES  (SMEM_FLOATS * 4 + CHUNK * 16 + CHUNK * 8)

__device__ float4 g_w   [EMAX];
__device__ int2   g_meta[EMAX];
__device__ int    g_count  [NMAX];
__device__ int    g_offsets[NMAX + 1];
__device__ int    g_cursor [NMAX];
__device__ int    g_bsum [NBMAX];
__device__ int    g_bexcl[NBMAX + 1];
__device__ uint4  g_kc[KSLICES * NTILES * 32];   // {hi.x, hi.y, lo.x, lo.y}

// ---------------------------------------------------------------------------
__global__ void zero_counts(int n) {
    int i = blockIdx.x * blockDim.x + threadIdx.x;
    if (i < n) g_count[i] = 0;
}

__global__ void count_edges(const int* __restrict__ receivers, int e) {
    int i = blockIdx.x * blockDim.x + threadIdx.x;
    if (i < e) atomicAdd(&g_count[receivers[i]], 1);
}

// ---- parallel scan: per-1024-block local scan ----
__global__ void scan_local(int n) {
    __shared__ int wsum[32];
    int tid = threadIdx.x, lane = tid & 31, wid = tid >> 5;
    int i = blockIdx.x * 1024 + tid;
    int v = (i < n) ? g_count[i] : 0;
    int x = v;
    #pragma unroll
    for (int d = 1; d < 32; d <<= 1) {
        int y = __shfl_up_sync(0xFFFFFFFFu, x, d);
        if (lane >= d) x += y;
    }
    if (lane == 31) wsum[wid] = x;
    __syncthreads();
    if (wid == 0) {
        int s = wsum[lane];
        #pragma unroll
        for (int d = 1; d < 32; d <<= 1) {
            int y = __shfl_up_sync(0xFFFFFFFFu, s, d);
            if (lane >= d) s += y;
        }
        wsum[lane] = s;
    }
    __syncthreads();
    int excl = (wid ? wsum[wid - 1] : 0) + (x - v);
    if (i < n) g_offsets[i] = excl;          // local exclusive
    if (tid == 0) g_bsum[blockIdx.x] = wsum[31];
}

// ---- scan of block sums (1 warp) ----
__global__ void scan_blocks(int nb) {
    int lane = threadIdx.x;
    int carry = 0;
    for (int base = 0; base < nb; base += 32) {
        int idx = base + lane;
        int v = (idx < nb) ? g_bsum[idx] : 0;
        int x = v;
        #pragma unroll
        for (int d = 1; d < 32; d <<= 1) {
            int y = __shfl_up_sync(0xFFFFFFFFu, x, d);
            if (lane >= d) x += y;
        }
        if (idx < nb) g_bexcl[idx] = carry + (x - v);
        carry += __shfl_sync(0xFFFFFFFFu, x, 31);
    }
    if (lane == 0) g_bexcl[nb] = carry;
}

// ---- add block offsets, produce final offsets + cursor ----
__global__ void scan_add(int n, int nb) {
    int i = blockIdx.x * blockDim.x + threadIdx.x;
    if (i < n) {
        int o = g_offsets[i] + g_bexcl[i >> 10];
        g_offsets[i] = o;
        g_cursor[i]  = o;
    }
    if (i == 0) g_offsets[n] = g_bexcl[nb];
}

// ---------------------------------------------------------------------------
__global__ void build_records(const int*   __restrict__ receivers,
                              const int*   __restrict__ senders,
                              const float* __restrict__ relpos,
                              const float* __restrict__ wsp,
                              int e) {
    int i = blockIdx.x * blockDim.x + threadIdx.x;
    if (i >= e) return;
    float ws = wsp[0];
    float rx = relpos[2 * i], ry = relpos[2 * i + 1];
    float ux = fminf(fmaxf(rx / ws, -1.0f), 1.0f);
    float uy = fminf(fmaxf(ry / ws, -1.0f), 1.0f);
    float gx = (ux + 1.0f) * 1.5f;
    float gy = (uy + 1.0f) * 1.5f;
    float x0f = fminf(fmaxf(floorf(gx), 0.0f), 2.0f);
    float y0f = fminf(fmaxf(floorf(gy), 0.0f), 2.0f);
    float fx = gx - x0f, fy = gy - y0f;
    float r2 = ux * ux + uy * uy;
    float wm = fmaxf(1.0f - r2, 0.0f);
    float win = wm * wm * wm;
    int x0 = (int)x0f, y0 = (int)y0f;
    int t0 = x0 * 4 + y0;

    float4 w = make_float4((1.0f - fx) * (1.0f - fy) * win,
                           (1.0f - fx) * fy          * win,
                           fx          * (1.0f - fy) * win,
                           fx          * fy          * win);
    int taps = t0 | ((t0 + 1) << 8) | ((t0 + 4) << 16) | ((t0 + 5) << 24);

    int r = receivers[i];
    int slot = atomicAdd(&g_cursor[r], 1);
    g_w[slot]    = w;
    g_meta[slot] = make_int2(senders[i], taps);
}

// ---------------------------------------------------------------------------
__device__ __forceinline__ float kfull_val(const float* __restrict__ kernelW,
                                           int k, int nn) {
    int tap = k >> 6, i = k & 63;
    int tx = tap >> 2, ty = tap & 3;
    if (ty < 2) return  kernelW[(tx * 2 + ty) * 4096 + i * 64 + nn];
    else        return -kernelW[((3 - tx) * 2 + (3 - ty)) * 4096 + i * 64 + nn];
}

__global__ void build_kcanon(const float* __restrict__ kernelW) {
    int idx = blockIdx.x * blockDim.x + threadIdx.x;   // 0 .. 16383
    if (idx >= KSLICES * NTILES * 32) return;
    int lane = idx & 31;
    int nt   = (idx >> 5) & 7;
    int s    = idx >> 8;
    int g = lane >> 2, c = lane & 3;
    int nn = nt * 8 + g;
    int k0 = s * 16 + 2 * c;

    float v0 = kfull_val(kernelW, k0,     nn);
    float v1 = kfull_val(kernelW, k0 + 1, nn);
    float v2 = kfull_val(kernelW, k0 + 8, nn);
    float v3 = kfull_val(kernelW, k0 + 9, nn);

    __nv_bfloat162 h01 = __floats2bfloat162_rn(v0, v1);
    __nv_bfloat162 h23 = __floats2bfloat162_rn(v2, v3);
    float h0 = __bfloat162float(__low2bfloat16(h01));
    float h1 = __bfloat162float(__high2bfloat16(h01));
    float h2 = __bfloat162float(__low2bfloat16(h23));
    float h3 = __bfloat162float(__high2bfloat16(h23));
    __nv_bfloat162 l01 = __floats2bfloat162_rn(v0 - h0, v1 - h1);
    __nv_bfloat162 l23 = __floats2bfloat162_rn(v2 - h2, v3 - h3);

    uint4 kv;
    kv.x = *reinterpret_cast<unsigned*>(&h01);
    kv.y = *reinterpret_cast<unsigned*>(&h23);
    kv.z = *reinterpret_cast<unsigned*>(&l01);
    kv.w = *reinterpret_cast<unsigned*>(&l23);
    g_kc[idx] = kv;
}

// ---------------------------------------------------------------------------
__device__ __forceinline__ void mma16816(float* d,
        unsigned a0, unsigned a1, unsigned a2, unsigned a3,
        unsigned b0, unsigned b1) {
    asm volatile(
        "mma.sync.aligned.m16n8k16.row.col.f32.bf16.bf16.f32 "
        "{%0,%1,%2,%3}, {%4,%5,%6,%7}, {%8,%9}, {%0,%1,%2,%3};"
        : "+f"(d[0]), "+f"(d[1]), "+f"(d[2]), "+f"(d[3])
        : "r"(a0), "r"(a1), "r"(a2), "r"(a3), "r"(b0), "r"(b1));
}

__global__ __launch_bounds__(256, 2)
void fused_conv_kernel(const float* __restrict__ features,
                       const float* __restrict__ bias,
                       float*       __restrict__ out,
                       int n) {
    extern __shared__ float smem[];
    float*  As = smem;                                   // MTILE * APAD
    float4* ws = (float4*)(smem + SMEM_FLOATS);          // CHUNK
    int2*   ms = (int2*)((char*)ws + CHUNK * 16);        // CHUNK

    int tid  = threadIdx.x;
    int lane = tid & 31, wid = tid >> 5;
    int nodeBase = blockIdx.x * MTILE;

    // zero accumulator tile (overlaps with first staged LDG below)
    for (int i = tid; i < SMEM_FLOATS; i += 256) As[i] = 0.0f;

    // warp's node pair (adjacent -> contiguous edge range)
    int n0 = min(nodeBase + 2 * wid,     n);
    int n1 = min(nodeBase + 2 * wid + 1, n);
    int n2 = min(nodeBase + 2 * wid + 2, n);
    int s   = g_offsets[n0];
    int mid = g_offsets[n1];
    int e2  = g_offsets[n2];
    float* Am0 = As + (2 * wid) * APAD;
    float* Am1 = Am0 + APAD;

    int o0 = g_offsets[nodeBase];
    int oE = g_offsets[min(nodeBase + MTILE, n)];

    // stage chunk 0 into registers (1 edge/thread)
    float4 rw = make_float4(0.f, 0.f, 0.f, 0.f);
    int2   rm = make_int2(0, 0);
    if (o0 + tid < oE) { rw = g_w[o0 + tid]; rm = g_meta[o0 + tid]; }

    // -------- Stage A: register-double-buffered chunks --------
    for (int cs = o0; cs < oE; cs += CHUNK) {
        if (cs + tid < oE) { ws[tid] = rw; ms[tid] = rm; }
        __syncthreads();
        // prefetch next chunk while applying this one
        int nx = cs + CHUNK + tid;
        if (nx < oE) { rw = g_w[nx]; rm = g_meta[nx]; }

        int js = max(s, cs), je = min(e2, cs + CHUNK);
        if (js < je) {
            float2 fbuf[FDEPTH];
            #pragma unroll
            for (int d = 0; d < FDEPTH; ++d) {
                if (js + d < je) {
                    int snd = ms[js + d - cs].x;
                    fbuf[d] = *(const float2*)(features + (size_t)snd * INC + lane * 2);
                }
            }
            for (int jb = js; jb < je; jb += FDEPTH) {
                #pragma unroll
                for (int d = 0; d < FDEPTH; ++d) {
                    int j = jb + d;
                    if (j >= je) break;
                    int li = j - cs;
                    float4 w4  = ws[li];
                    int    tps = ms[li].y;
                    float2 f   = fbuf[d];
                    int jn = j + FDEPTH;
                    if (jn < je) {
                        int snd = ms[jn - cs].x;
                        fbuf[d] = *(const float2*)(features + (size_t)snd * INC + lane * 2);
                    }
                    float* Am = (j < mid) ? Am0 : Am1;
                    // taps t0, t0+1, t0+4, t0+5 are pairwise distinct:
                    // batch loads -> fmas -> stores (one LDS latency per edge)
                    float2* p0 = (float2*)(Am + (tps         & 0xFF) * 64) + lane;
                    float2* p1 = (float2*)(Am + ((tps >>  8) & 0xFF) * 64) + lane;
                    float2* p2 = (float2*)(Am + ((tps >> 16) & 0xFF) * 64) + lane;
                    float2* p3 = (float2*)(Am + ((tps >> 24) & 0xFF) * 64) + lane;
                    float2 v0 = *p0, v1 = *p1, v2 = *p2, v3 = *p3;
                    v0.x += w4.x * f.x; v0.y += w4.x * f.y;
                    v1.x += w4.y * f.x; v1.y += w4.y * f.y;
                    v2.x += w4.z * f.x; v2.y += w4.z * f.y;
                    v3.x += w4.w * f.x; v3.y += w4.w * f.y;
                    *p0 = v0; *p1 = v1; *p2 = v2; *p3 = v3;
                }
            }
        }
        __syncthreads();
    }
    __syncthreads();

    // -------- Convert A in place: fp32 pair -> (hi bf16x2, lo bf16x2) -------
    for (int i = tid; i < MTILE * 512; i += 256) {
        int m = i >> 9;
        int j = i & 511;
        float* p = As + m * APAD + 2 * j;
        float2 v = *(float2*)p;
        __nv_bfloat162 h2 = __floats2bfloat162_rn(v.x, v.y);
        float h0 = __bfloat162float(__low2bfloat16(h2));
        float h1 = __bfloat162float(__high2bfloat16(h2));
        __nv_bfloat162 l2 = __floats2bfloat162_rn(v.x - h0, v.y - h1);
        uint2 w;
        w.x = *reinterpret_cast<unsigned*>(&h2);
        w.y = *reinterpret_cast<unsigned*>(&l2);
        *(uint2*)p = w;
    }
    __syncthreads();

    // -------- Stage B: split-bf16 tensor-core contraction --------
    int nt = wid;
    int g = lane >> 2, c = lane & 3;
    const float* rowA  = As + g * APAD;
    const float* rowA8 = rowA + 8 * APAD;

    float d0[4] = {0.f, 0.f, 0.f, 0.f};

    uint4 kb[4];
    #pragma unroll
    for (int d = 0; d < 4; ++d)
        kb[d] = g_kc[(d * NTILES + nt) * 32 + lane];

    for (int sb = 0; sb < KSLICES; sb += 4) {
        #pragma unroll
        for (int d = 0; d < 4; ++d) {
            int sl = sb + d;
            uint4 kv = kb[d];
            if (sl + 4 < KSLICES)
                kb[d] = g_kc[((sl + 4) * NTILES + nt) * 32 + lane];
            const float* pa = rowA  + 16 * sl + 2 * c;
            const float* pb = rowA8 + 16 * sl + 2 * c;
            uint2 A0 = *(const uint2*)(pa);
            uint2 A1 = *(const uint2*)(pb);
            uint2 A2 = *(const uint2*)(pa + 8);
            uint2 A3 = *(const uint2*)(pb + 8);
            // D += Ahi*Khi + Ahi*Klo + Alo*Khi
            mma16816(d0, A0.x, A1.x, A2.x, A3.x, kv.x, kv.y);
            mma16816(d0, A0.x, A1.x, A2.x, A3.x, kv.z, kv.w);
            mma16816(d0, A0.y, A1.y, A2.y, A3.y, kv.x, kv.y);
        }
    }

    // -------- store D + bias --------
    int node0 = nodeBase + g;
    int node8 = node0 + 8;
    int o = nt * 8 + 2 * c;
    float2 b = *(const float2*)(bias + o);
    if (node0 < n) {
        float2 r = make_float2(d0[0] + b.x, d0[1] + b.y);
        *(float2*)(out + (size_t)node0 * OUTC + o) = r;
    }
    if (node8 < n) {
        float2 r = make_float2(d0[2] + b.x, d0[3] + b.y);
        *(float2*)(out + (size_t)node8 * OUTC + o) = r;
    }
}

// ---------------------------------------------------------------------------
extern "C" void kernel_launch(void* const* d_in, const int* in_sizes, int n_in,
                              void* d_out, int out_size) {
    const float* features  = (const float*)d_in[0];
    const int*   receivers = (const int*)  d_in[1];
    const float* relpos    = (const float*)d_in[2];
    const float* wsp       = (const float*)d_in[3];
    const int*   senders   = (const int*)  d_in[4];
    const float* kernelW   = (const float*)d_in[5];
    const float* bias      = (const float*)d_in[6];
    float*       out       = (float*)d_out;

    int n = in_sizes[0] / INC;   // 50000
    int e = in_sizes[1];         // 800000
    int nb = (n + 1023) / 1024;

    cudaFuncSetAttribute(fused_conv_kernel,
                         cudaFuncAttributeMaxDynamicSharedMemorySize, SMEM_BYTES);

    zero_counts  <<<(n + 255) / 256, 256>>>(n);
    count_edges  <<<(e + 255) / 256, 256>>>(receivers, e);
    scan_local   <<<nb, 1024>>>(n);
    scan_blocks  <<<1, 32>>>(nb);
    scan_add     <<<(n + 255) / 256, 256>>>(n, nb);
    build_records<<<(e + 255) / 256, 256>>>(receivers, senders, relpos, wsp, e);
    build_kcanon <<<(KSLICES * NTILES * 32 + 255) / 256, 256>>>(kernelW);

    int blocks = (n + MTILE - 1) / MTILE;
    fused_conv_kernel<<<blocks, 256, SMEM_BYTES>>>(features, bias, out, n);
}